// round 8
// baseline (speedup 1.0000x reference)
#include <cuda_runtime.h>

// Fused GwcVolumeCostProcessor: out [1, 64, 48, 128, 240] f32
//   ch 0..39  : groupwise correlation (mean over 8 ch of ref_gwc * shift(tgt_gwc,d))
//   ch 40..51 : ref_concat * (w >= d)
//   ch 52..63 : shift(tgt_concat, d)

#define HH 128
#define WW 240
#define DD 48
#define NG 40
#define CPG 8
#define HW (HH * WW)
#define W4 60                    // float4s per row
#define PAD 48                   // left zero-pad for tgt window
#define TW (PAD + WW)            // 288 padded row
#define NQ (DD / 4)              // 12 disparity quads
#define K_TILES 4
#define GWC_TILES (NG * HH)      // 5120
#define GWC_PB (GWC_TILES / K_TILES) // 1280 gwc blocks
#define CAT_BLOCKS (24 * DD * 2)     // 2304 : (c, d, h-half)

__device__ __forceinline__ void cpa16(void* smem_dst, const void* gsrc) {
    unsigned sa = (unsigned)__cvta_generic_to_shared(smem_dst);
    asm volatile("cp.async.cg.shared.global [%0], [%1], 16;" :: "r"(sa), "l"(gsrc));
}

__global__ __launch_bounds__(64, 12) void fused_kernel(
    const float* __restrict__ ref, const float* __restrict__ tgt,
    const float* __restrict__ refc, const float* __restrict__ tgtc,
    float* __restrict__ out)
{
    __shared__ __align__(16) float stgt[2][CPG][TW];   // double-buffered padded tgt rows

    const int bid = blockIdx.x;
    const int tid = threadIdx.x;

    if (bid < GWC_PB) {
        // ============ gwc: K_TILES tiles per block, pipelined ============

        // zero the pad regions of both buffers once (2*8*12 = 192 float4)
#pragma unroll
        for (int i = tid; i < 2 * CPG * (PAD / 4); i += 64) {
            int b = i / (CPG * (PAD / 4));
            int r = i - b * (CPG * (PAD / 4));
            int c = r / (PAD / 4);
            int x = r - c * (PAD / 4);
            *(float4*)&stgt[b][c][x * 4] = make_float4(0.f, 0.f, 0.f, 0.f);
        }

        const int tile0 = bid * K_TILES;

        // prefetch tile0 into buf 0 : 8 channels x 60 float4
        {
            int g = tile0 >> 7, h = tile0 & 127;
            const float* tp = tgt + ((size_t)g * CPG) * HW + (size_t)h * WW;
            for (int i = tid; i < CPG * W4; i += 64) {
                int c = i / W4;
                int x = i - c * W4;
                cpa16(&stgt[0][c][PAD + 4 * x], tp + (size_t)c * HW + 4 * x);
            }
            asm volatile("cp.async.commit_group;" ::: "memory");
        }

        for (int t = 0; t < K_TILES; t++) {
            asm volatile("cp.async.wait_group 0;" ::: "memory");
            __syncthreads();   // tile t data visible; everyone done with buf (t+1)&1

            if (t + 1 < K_TILES) {   // prefetch next tile, overlapped with compute
                int tile = tile0 + t + 1;
                int g = tile >> 7, h = tile & 127;
                const float* tp = tgt + ((size_t)g * CPG) * HW + (size_t)h * WW;
                float* dst0 = &stgt[(t + 1) & 1][0][0];
                for (int i = tid; i < CPG * W4; i += 64) {
                    int c = i / W4;
                    int x = i - c * W4;
                    cpa16(dst0 + c * TW + PAD + 4 * x, tp + (size_t)c * HW + 4 * x);
                }
                asm volatile("cp.async.commit_group;" ::: "memory");
            }

            if (tid < W4) {
                const int tile = tile0 + t;
                const int g = tile >> 7, h = tile & 127;
                const int w4 = tid * 4;
                const float (*buf)[TW] = stgt[t & 1];

                // ref channel values -> registers, pre-scaled by 1/8
                const float* refp = ref + ((size_t)g * CPG) * HW + (size_t)h * WW + w4;
                float4 r[CPG];
#pragma unroll
                for (int c = 0; c < CPG; c++) {
                    float4 v = *(const float4*)(refp + (size_t)c * HW);
                    v.x *= 0.125f; v.y *= 0.125f; v.z *= 0.125f; v.w *= 0.125f;
                    r[c] = v;
                }

                const int base = (PAD / 4) + tid;   // float4 index at d=0
                float4 win[CPG];
#pragma unroll
                for (int c = 0; c < CPG; c++)
                    win[c] = ((const float4*)buf[c])[base];

                float* op = out + (((size_t)g * DD) * HH + h) * WW + w4;

#pragma unroll 2
                for (int q = 1; q <= NQ; q++) {
                    float4 nxt[CPG];
#pragma unroll
                    for (int c = 0; c < CPG; c++)
                        nxt[c] = ((const float4*)buf[c])[base - q];

                    float4 a;
                    // d = 4(q-1)+0 : window = win
                    a = make_float4(0.f, 0.f, 0.f, 0.f);
#pragma unroll
                    for (int c = 0; c < CPG; c++) {
                        a.x += r[c].x * win[c].x; a.y += r[c].y * win[c].y;
                        a.z += r[c].z * win[c].z; a.w += r[c].w * win[c].w;
                    }
                    *(float4*)op = a; op += HW;

                    // +1 : (nxt.w, win.x, win.y, win.z)
                    a = make_float4(0.f, 0.f, 0.f, 0.f);
#pragma unroll
                    for (int c = 0; c < CPG; c++) {
                        a.x += r[c].x * nxt[c].w; a.y += r[c].y * win[c].x;
                        a.z += r[c].z * win[c].y; a.w += r[c].w * win[c].z;
                    }
                    *(float4*)op = a; op += HW;

                    // +2 : (nxt.z, nxt.w, win.x, win.y)
                    a = make_float4(0.f, 0.f, 0.f, 0.f);
#pragma unroll
                    for (int c = 0; c < CPG; c++) {
                        a.x += r[c].x * nxt[c].z; a.y += r[c].y * nxt[c].w;
                        a.z += r[c].z * win[c].x; a.w += r[c].w * win[c].y;
                    }
                    *(float4*)op = a; op += HW;

                    // +3 : (nxt.y, nxt.z, nxt.w, win.x)
                    a = make_float4(0.f, 0.f, 0.f, 0.f);
#pragma unroll
                    for (int c = 0; c < CPG; c++) {
                        a.x += r[c].x * nxt[c].y; a.y += r[c].y * nxt[c].z;
                        a.z += r[c].z * nxt[c].w; a.w += r[c].w * win[c].x;
                    }
                    *(float4*)op = a; op += HW;

#pragma unroll
                    for (int c = 0; c < CPG; c++) win[c] = nxt[c];
                }
            }
        }
    } else {
        // ============ concat: one block per (c, d, h-half) ============
        const int id   = bid - GWC_PB;
        const int c    = id / (DD * 2);
        const int rem  = id - c * (DD * 2);
        const int d    = rem >> 1;
        const int half = rem & 1;

        float* op = out + (size_t)(NG + c) * DD * HW + (size_t)d * HW
                        + (size_t)half * 64 * WW;

        if (c < 12) {
            const float* rp = refc + (size_t)c * HW + (size_t)half * 64 * WW;
#pragma unroll 4
            for (int i = tid; i < 64 * W4; i += 64) {
                int h  = i / W4;
                int w4 = (i - h * W4) * 4;
                float4 v = *(const float4*)(rp + h * WW + w4);
                if (w4 < d) {
                    if (w4 + 0 < d) v.x = 0.f;
                    if (w4 + 1 < d) v.y = 0.f;
                    if (w4 + 2 < d) v.z = 0.f;
                    if (w4 + 3 < d) v.w = 0.f;
                }
                *(float4*)(op + h * WW + w4) = v;
            }
        } else {
            const float* tp = tgtc + (size_t)(c - 12) * HW + (size_t)half * 64 * WW;
#pragma unroll 4
            for (int i = tid; i < 64 * W4; i += 64) {
                int h  = i / W4;
                int w4 = (i - h * W4) * 4;
                const float* row = tp + h * WW;
                float4 v;
                v.x = (w4 + 0 >= d) ? row[w4 + 0 - d] : 0.f;
                v.y = (w4 + 1 >= d) ? row[w4 + 1 - d] : 0.f;
                v.z = (w4 + 2 >= d) ? row[w4 + 2 - d] : 0.f;
                v.w = (w4 + 3 >= d) ? row[w4 + 3 - d] : 0.f;
                *(float4*)(op + h * WW + w4) = v;
            }
        }
    }
}

extern "C" void kernel_launch(void* const* d_in, const int* in_sizes, int n_in,
                              void* d_out, int out_size)
{
    const float* ref_gwc    = (const float*)d_in[0];
    const float* tgt_gwc    = (const float*)d_in[1];
    const float* ref_concat = (const float*)d_in[2];
    const float* tgt_concat = (const float*)d_in[3];
    float* out = (float*)d_out;

    fused_kernel<<<GWC_PB + CAT_BLOCKS, 64>>>(
        ref_gwc, tgt_gwc, ref_concat, tgt_concat, out);
}

// round 11
// speedup vs baseline: 1.4423x; 1.4423x over previous
#include <cuda_runtime.h>

// Fused GwcVolumeCostProcessor: out [1, 64, 48, 128, 240] f32
//   ch 0..39  : groupwise correlation (mean over 8 ch of ref_gwc * shift(tgt_gwc,d))
//   ch 40..51 : ref_concat * (w >= d)
//   ch 52..63 : shift(tgt_concat, d)

#define HH 128
#define WW 240
#define DD 48
#define NG 40
#define CPG 8
#define HW (HH * WW)
#define W4 60                    // float4s per row
#define PAD 48                   // left zero-pad for tgt window
#define TW (PAD + WW)            // 288 padded row
#define GWC_BLOCKS (NG * HH)     // 5120
#define CAT_BLOCKS (24 * DD * 2) // 2304 : (c, d, h-half)

__device__ __forceinline__ void cpa16(void* smem_dst, const void* gsrc) {
    unsigned sa = (unsigned)__cvta_generic_to_shared(smem_dst);
    asm volatile("cp.async.cg.shared.global [%0], [%1], 16;" :: "r"(sa), "l"(gsrc));
}

__global__ __launch_bounds__(64) void fused_kernel(
    const float* __restrict__ ref, const float* __restrict__ tgt,
    const float* __restrict__ refc, const float* __restrict__ tgtc,
    float* __restrict__ out)
{
    __shared__ __align__(16) float stgt[CPG][TW];

    const int bid = blockIdx.x;
    const int tid = threadIdx.x;

    if (bid < GWC_BLOCKS) {
        // ---------------- gwc: one block per (group, h-row) ----------------
        const int g = bid >> 7;
        const int h = bid & 127;
        const int w4 = tid * 4;

        // (1) issue ref LDGs FIRST — latency hides under fill + barrier
        const float* refp = ref + ((size_t)g * CPG) * HW + (size_t)h * WW + w4;
        float4 r[CPG];
        if (tid < W4) {
#pragma unroll
            for (int c = 0; c < CPG; c++)
                r[c] = *(const float4*)(refp + (size_t)c * HW);
        }

        // zero left pad: 8 ch x 12 float4
        for (int i = tid; i < CPG * (PAD / 4); i += 64) {
            int c = i / (PAD / 4);
            int x = i - c * (PAD / 4);
            *(float4*)&stgt[c][x * 4] = make_float4(0.f, 0.f, 0.f, 0.f);
        }

        // (2) cp.async fill of tgt rows: 8 ch x 60 float4
        const float* tgtp = tgt + ((size_t)g * CPG) * HW + (size_t)h * WW;
        for (int i = tid; i < CPG * W4; i += 64) {
            int c = i / W4;
            int x = i - c * W4;
            cpa16(&stgt[c][PAD + 4 * x], tgtp + (size_t)c * HW + 4 * x);
        }
        asm volatile("cp.async.commit_group;" ::: "memory");
        asm volatile("cp.async.wait_group 0;" ::: "memory");
        __syncthreads();

        if (tid >= W4) return;

        // pre-scale ref by 1/8 (after the overlap window)
#pragma unroll
        for (int c = 0; c < CPG; c++) {
            r[c].x *= 0.125f; r[c].y *= 0.125f; r[c].z *= 0.125f; r[c].w *= 0.125f;
        }

        // sliding window: win[c][k] = stgt[c][PAD + w4 - d + k]
        float win[CPG][4];
#pragma unroll
        for (int c = 0; c < CPG; c++) {
            float4 v = *(const float4*)&stgt[c][PAD + w4];
            win[c][0] = v.x; win[c][1] = v.y; win[c][2] = v.z; win[c][3] = v.w;
        }

        float* op = out + (((size_t)g * DD) * HH + h) * WW + w4;
#pragma unroll 4
        for (int d = 0; d < DD; d++) {
            float4 acc = make_float4(0.f, 0.f, 0.f, 0.f);
#pragma unroll
            for (int c = 0; c < CPG; c++) {
                acc.x += r[c].x * win[c][0];
                acc.y += r[c].y * win[c][1];
                acc.z += r[c].z * win[c][2];
                acc.w += r[c].w * win[c][3];
            }
            __stcs((float4*)op, acc);   // (3) evict-first streaming store
            op += HW;

            // shift window for d+1 (unroll-4 -> register renames)
#pragma unroll
            for (int c = 0; c < CPG; c++) {
                win[c][3] = win[c][2];
                win[c][2] = win[c][1];
                win[c][1] = win[c][0];
                win[c][0] = stgt[c][PAD + w4 - (d + 1)];
            }
        }
    } else {
        // ---------------- concat: one block per (c, d, h-half) ----------------
        const int id   = bid - GWC_BLOCKS;
        const int c    = id / (DD * 2);
        const int rem  = id - c * (DD * 2);
        const int d    = rem >> 1;
        const int half = rem & 1;

        float* op = out + (size_t)(NG + c) * DD * HW + (size_t)d * HW
                        + (size_t)half * 64 * WW;

        if (c < 12) {
            const float* rp = refc + (size_t)c * HW + (size_t)half * 64 * WW;
            for (int i = tid; i < 64 * W4; i += 64) {
                int h  = i / W4;
                int w4 = (i - h * W4) * 4;
                float4 v = *(const float4*)(rp + h * WW + w4);
                if (w4 < d) {
                    if (w4 + 0 < d) v.x = 0.f;
                    if (w4 + 1 < d) v.y = 0.f;
                    if (w4 + 2 < d) v.z = 0.f;
                    if (w4 + 3 < d) v.w = 0.f;
                }
                __stcs((float4*)(op + h * WW + w4), v);
            }
        } else {
            const float* tp = tgtc + (size_t)(c - 12) * HW + (size_t)half * 64 * WW;
            for (int i = tid; i < 64 * W4; i += 64) {
                int h  = i / W4;
                int w4 = (i - h * W4) * 4;
                const float* row = tp + h * WW;
                float4 v;
                v.x = (w4 + 0 >= d) ? row[w4 + 0 - d] : 0.f;
                v.y = (w4 + 1 >= d) ? row[w4 + 1 - d] : 0.f;
                v.z = (w4 + 2 >= d) ? row[w4 + 2 - d] : 0.f;
                v.w = (w4 + 3 >= d) ? row[w4 + 3 - d] : 0.f;
                __stcs((float4*)(op + h * WW + w4), v);
            }
        }
    }
}

extern "C" void kernel_launch(void* const* d_in, const int* in_sizes, int n_in,
                              void* d_out, int out_size)
{
    const float* ref_gwc    = (const float*)d_in[0];
    const float* tgt_gwc    = (const float*)d_in[1];
    const float* ref_concat = (const float*)d_in[2];
    const float* tgt_concat = (const float*)d_in[3];
    float* out = (float*)d_out;

    fused_kernel<<<GWC_BLOCKS + CAT_BLOCKS, 64>>>(
        ref_gwc, tgt_gwc, ref_concat, tgt_concat, out);
}

// round 12
// speedup vs baseline: 1.5265x; 1.0584x over previous
#include <cuda_runtime.h>

// Fused GwcVolumeCostProcessor: out [1, 64, 48, 128, 240] f32
//   ch 0..39  : groupwise correlation (mean over 8 ch of ref_gwc * shift(tgt_gwc,d))
//   ch 40..51 : ref_concat * (w >= d)
//   ch 52..63 : shift(tgt_concat, d)

#define HH 128
#define WW 240
#define DD 48
#define NG 40
#define CPG 8
#define HW (HH * WW)
#define W4 60                    // float4s per row
#define PAD 48                   // left zero-pad for tgt window
#define TW (PAD + WW)            // 288 padded row
#define GWC_BLOCKS (NG * HH)     // 5120
#define CAT_BLOCKS (24 * DD * 2) // 2304 : (c, d, h-half)
#define TOT_BLOCKS (GWC_BLOCKS + CAT_BLOCKS) // 7424

__device__ __forceinline__ void cpa16(void* smem_dst, const void* gsrc) {
    unsigned sa = (unsigned)__cvta_generic_to_shared(smem_dst);
    asm volatile("cp.async.cg.shared.global [%0], [%1], 16;" :: "r"(sa), "l"(gsrc));
}

__global__ __launch_bounds__(64) void fused_kernel(
    const float* __restrict__ ref, const float* __restrict__ tgt,
    const float* __restrict__ refc, const float* __restrict__ tgtc,
    float* __restrict__ out)
{
    __shared__ __align__(16) float stgt[CPG][TW];

    const int bid = blockIdx.x;
    const int tid = threadIdx.x;

    // Bresenham interleave: spread CAT_BLOCKS evenly across the grid.
    // cats_before = floor(bid * 9 / 29)  (2304/7424 = 9/29, exact)
    const int cats_before = (int)(((long long)bid * 9) / 29);
    const int cats_next   = (int)(((long long)(bid + 1) * 9) / 29);
    const bool is_cat = (cats_next > cats_before);

    if (!is_cat) {
        // ---------------- gwc: one block per (group, h-row) ----------------
        const int id = bid - cats_before;
        const int g = id >> 7;
        const int h = id & 127;
        const int w4 = tid * 4;

        // (1) issue ref LDGs FIRST — latency hides under fill + barrier.
        //     __ldcs: single-use data, keep L2 for the reused concat inputs.
        const float* refp = ref + ((size_t)g * CPG) * HW + (size_t)h * WW + w4;
        float4 r[CPG];
        if (tid < W4) {
#pragma unroll
            for (int c = 0; c < CPG; c++)
                r[c] = __ldcs((const float4*)(refp + (size_t)c * HW));
        }

        // zero left pad: 8 ch x 12 float4
        for (int i = tid; i < CPG * (PAD / 4); i += 64) {
            int c = i / (PAD / 4);
            int x = i - c * (PAD / 4);
            *(float4*)&stgt[c][x * 4] = make_float4(0.f, 0.f, 0.f, 0.f);
        }

        // (2) cp.async fill of tgt rows: 8 ch x 60 float4
        const float* tgtp = tgt + ((size_t)g * CPG) * HW + (size_t)h * WW;
        for (int i = tid; i < CPG * W4; i += 64) {
            int c = i / W4;
            int x = i - c * W4;
            cpa16(&stgt[c][PAD + 4 * x], tgtp + (size_t)c * HW + 4 * x);
        }
        asm volatile("cp.async.commit_group;" ::: "memory");
        asm volatile("cp.async.wait_group 0;" ::: "memory");
        __syncthreads();

        if (tid >= W4) return;

        // pre-scale ref by 1/8 (after the overlap window)
#pragma unroll
        for (int c = 0; c < CPG; c++) {
            r[c].x *= 0.125f; r[c].y *= 0.125f; r[c].z *= 0.125f; r[c].w *= 0.125f;
        }

        // sliding window: win[c][k] = stgt[c][PAD + w4 - d + k]
        float win[CPG][4];
#pragma unroll
        for (int c = 0; c < CPG; c++) {
            float4 v = *(const float4*)&stgt[c][PAD + w4];
            win[c][0] = v.x; win[c][1] = v.y; win[c][2] = v.z; win[c][3] = v.w;
        }

        float* op = out + (((size_t)g * DD) * HH + h) * WW + w4;
#pragma unroll 4
        for (int d = 0; d < DD; d++) {
            float4 acc = make_float4(0.f, 0.f, 0.f, 0.f);
#pragma unroll
            for (int c = 0; c < CPG; c++) {
                acc.x += r[c].x * win[c][0];
                acc.y += r[c].y * win[c][1];
                acc.z += r[c].z * win[c][2];
                acc.w += r[c].w * win[c][3];
            }
            __stcs((float4*)op, acc);   // (3) evict-first streaming store
            op += HW;

            // shift window for d+1 (unroll-4 -> register renames)
#pragma unroll
            for (int c = 0; c < CPG; c++) {
                win[c][3] = win[c][2];
                win[c][2] = win[c][1];
                win[c][1] = win[c][0];
                win[c][0] = stgt[c][PAD + w4 - (d + 1)];
            }
        }
    } else {
        // ---------------- concat: one block per (c, d, h-half) ----------------
        const int id   = cats_before;
        const int c    = id / (DD * 2);
        const int rem  = id - c * (DD * 2);
        const int d    = rem >> 1;
        const int half = rem & 1;

        float* op = out + (size_t)(NG + c) * DD * HW + (size_t)d * HW
                        + (size_t)half * 64 * WW;

        if (c < 12) {
            const float* rp = refc + (size_t)c * HW + (size_t)half * 64 * WW;
            for (int i = tid; i < 64 * W4; i += 64) {
                int h  = i / W4;
                int w4 = (i - h * W4) * 4;
                float4 v = *(const float4*)(rp + h * WW + w4);
                if (w4 < d) {
                    if (w4 + 0 < d) v.x = 0.f;
                    if (w4 + 1 < d) v.y = 0.f;
                    if (w4 + 2 < d) v.z = 0.f;
                    if (w4 + 3 < d) v.w = 0.f;
                }
                __stcs((float4*)(op + h * WW + w4), v);
            }
        } else {
            const float* tp = tgtc + (size_t)(c - 12) * HW + (size_t)half * 64 * WW;
            for (int i = tid; i < 64 * W4; i += 64) {
                int h  = i / W4;
                int w4 = (i - h * W4) * 4;
                const float* row = tp + h * WW;
                float4 v;
                v.x = (w4 + 0 >= d) ? row[w4 + 0 - d] : 0.f;
                v.y = (w4 + 1 >= d) ? row[w4 + 1 - d] : 0.f;
                v.z = (w4 + 2 >= d) ? row[w4 + 2 - d] : 0.f;
                v.w = (w4 + 3 >= d) ? row[w4 + 3 - d] : 0.f;
                __stcs((float4*)(op + h * WW + w4), v);
            }
        }
    }
}

extern "C" void kernel_launch(void* const* d_in, const int* in_sizes, int n_in,
                              void* d_out, int out_size)
{
    const float* ref_gwc    = (const float*)d_in[0];
    const float* tgt_gwc    = (const float*)d_in[1];
    const float* ref_concat = (const float*)d_in[2];
    const float* tgt_concat = (const float*)d_in[3];
    float* out = (float*)d_out;

    fused_kernel<<<TOT_BLOCKS, 64>>>(
        ref_gwc, tgt_gwc, ref_concat, tgt_concat, out);
}